// round 9
// baseline (speedup 1.0000x reference)
#include <cuda_runtime.h>
#include <cuda_fp16.h>
#include <cstdint>

#define BATCH   512
#define MEM     256            // K dimension
#define FEAT    512
#define NCOL    131072         // 64*2048
#define TOPK    16

#define NCHUNK  64             // N columns per gemm work item
#define NCHUNKS (NCOL / NCHUNK)     // 2048
#define MTILE   256            // M rows per gemm CTA (one half)
#define GT      512            // gemm threads (16 warps)

#define BPAD    72             // halfs per B k-row in smem (64 + 8 pad)
#define B_BUF   (64 * BPAD)    // halfs per B k-chunk buffer (4608)
#define A_HALFS (MTILE * MEM)  // 65536 halfs = 131072 B, swizzled, no pad
#define DYN_SMEM ((A_HALFS + 2 * B_BUF) * 2)   // 149504 bytes -> 1 CTA/SM

// Dense fp16 weight matrix W[512][256], linear row-major. Built by kernel 1.
__device__ __align__(16) __half g_W[BATCH * MEM];

// ---------------------------------------------------------------------------
// Kernel 1: cosine sim + top-16 + clamp + renormalize -> dense fp16 W.
// (unchanged)
// ---------------------------------------------------------------------------
__global__ void __launch_bounds__(256)
topk_kernel(const float* __restrict__ features, const float* __restrict__ keys) {
    __shared__ float f_s[4 * FEAT];
    __shared__ float fn_s[4];
    __shared__ float sim_s[4 * 264];
    __shared__ float topv_s[4][TOPK];
    __shared__ int   topi_s[4][TOPK];
    __shared__ float w_dense[4][MEM];

    const int t    = threadIdx.x;
    const int warp = t >> 5;
    const int lane = t & 31;
    const int base = blockIdx.x * 4;

    float4* f4s = reinterpret_cast<float4*>(f_s);
    const float4* fg = reinterpret_cast<const float4*>(features) + (size_t)base * (FEAT / 4);
    for (int i = t; i < 4 * FEAT / 4; i += 256) f4s[i] = fg[i];
    __syncthreads();

    if (warp < 4) {
        float s = 0.f;
#pragma unroll
        for (int m = 0; m < FEAT / 32; m++) {
            float v = f_s[warp * FEAT + lane + m * 32];
            s += v * v;
        }
#pragma unroll
        for (int off = 16; off; off >>= 1) s += __shfl_down_sync(0xffffffffu, s, off);
        if (lane == 0) fn_s[warp] = fmaxf(sqrtf(s), 1e-8f);
    }
    __syncthreads();

    const float4* krow = reinterpret_cast<const float4*>(keys) + (size_t)t * (FEAT / 4);
    float acc[4] = {0.f, 0.f, 0.f, 0.f};
    float kn = 0.f;
#pragma unroll 4
    for (int d = 0; d < FEAT / 4; d++) {
        float4 kv = krow[d];
        kn += kv.x * kv.x + kv.y * kv.y + kv.z * kv.z + kv.w * kv.w;
#pragma unroll
        for (int b = 0; b < 4; b++) {
            float4 fv = f4s[b * (FEAT / 4) + d];
            acc[b] += kv.x * fv.x + kv.y * fv.y + kv.z * fv.z + kv.w * fv.w;
        }
    }
    const float rkn = fmaxf(sqrtf(kn), 1e-8f);
#pragma unroll
    for (int b = 0; b < 4; b++)
        sim_s[b * 264 + t] = acc[b] / (fn_s[b] * rkn);

#pragma unroll
    for (int r = 0; r < 4; r++) w_dense[r][t] = 0.f;
    __syncthreads();

    if (warp < 4) {
        float v[8];
#pragma unroll
        for (int m = 0; m < 8; m++) v[m] = sim_s[warp * 264 + lane * 8 + m];

        for (int k = 0; k < TOPK; k++) {
            float best = v[0];
            int bm = 0;
#pragma unroll
            for (int m = 1; m < 8; m++)
                if (v[m] > best) { best = v[m]; bm = m; }
            int gi = lane * 8 + bm;
#pragma unroll
            for (int off = 16; off; off >>= 1) {
                float ov = __shfl_down_sync(0xffffffffu, best, off);
                int   oi = __shfl_down_sync(0xffffffffu, gi,   off);
                if (ov > best || (ov == best && oi < gi)) { best = ov; gi = oi; }
            }
            best = __shfl_sync(0xffffffffu, best, 0);
            gi   = __shfl_sync(0xffffffffu, gi,   0);
            if (lane == (gi >> 3)) {
                int li = gi & 7;
#pragma unroll
                for (int m = 0; m < 8; m++)
                    if (m == li) v[m] = -3.0e38f;
            }
            if (lane == 0) { topv_s[warp][k] = best; topi_s[warp][k] = gi; }
        }
        __syncwarp();

        float tv = (lane < TOPK) ? fmaxf(topv_s[warp][lane], 0.f) : 0.f;
        float s = tv;
#pragma unroll
        for (int off = 16; off; off >>= 1) s += __shfl_down_sync(0xffffffffu, s, off);
        s = __shfl_sync(0xffffffffu, s, 0);
        const float inv = 1.0f / s;
        if (lane < TOPK)
            w_dense[warp][topi_s[warp][lane]] = tv * inv;
    }
    __syncthreads();

#pragma unroll
    for (int r = 0; r < 4; r++)
        g_W[(base + r) * MEM + t] = __float2half_rn(w_dense[r][t]);
}

// ---------------------------------------------------------------------------
// Kernel 2: persistent HMMA GEMM, 1 CTA/SM.
// CTA bid: mhalf = bid&1, pairIdx = bid>>1. A (its 256x256 W half) loaded
// ONCE into XOR-swizzled SMEM; CTA then loops over chunks pairIdx + j*PAIRS
// with a continuous double-buffered B pipeline (LDG ahead -> cvt -> STS).
// CTA pairs (2p, 2p+1) walk the same chunk list => B's 2nd read is an L2 hit.
// 16 warps, warp tile 32M x 32N.
// ---------------------------------------------------------------------------
__device__ __forceinline__ void mma16816(float d[4],
                                         uint32_t a0, uint32_t a1, uint32_t a2, uint32_t a3,
                                         uint32_t b0, uint32_t b1) {
    asm volatile(
        "mma.sync.aligned.m16n8k16.row.col.f32.f16.f16.f32 "
        "{%0,%1,%2,%3}, {%4,%5,%6,%7}, {%8,%9}, {%0,%1,%2,%3};"
        : "+f"(d[0]), "+f"(d[1]), "+f"(d[2]), "+f"(d[3])
        : "r"(a0), "r"(a1), "r"(a2), "r"(a3), "r"(b0), "r"(b1));
}
__device__ __forceinline__ void ldsm_x4(uint32_t r[4], uint32_t sa) {
    asm volatile("ldmatrix.sync.aligned.m8n8.x4.shared.b16 {%0,%1,%2,%3}, [%4];"
        : "=r"(r[0]), "=r"(r[1]), "=r"(r[2]), "=r"(r[3]) : "r"(sa));
}
__device__ __forceinline__ void ldsm_x4_t(uint32_t r[4], uint32_t sa) {
    asm volatile("ldmatrix.sync.aligned.m8n8.x4.trans.shared.b16 {%0,%1,%2,%3}, [%4];"
        : "=r"(r[0]), "=r"(r[1]), "=r"(r[2]), "=r"(r[3]) : "r"(sa));
}
__device__ __forceinline__ void stg_cs_v2(float* p, float2 v) {
    asm volatile("st.global.cs.v2.f32 [%0], {%1, %2};" :: "l"(p), "f"(v.x), "f"(v.y) : "memory");
}

__global__ void __launch_bounds__(GT, 1)
gemm_kernel(const float* __restrict__ memory, float* __restrict__ out, int pairs) {
    extern __shared__ __half sm[];
    __half* As = sm;                    // [256][256] swizzled (no pad)
    __half* Bs = sm + A_HALFS;          // [2][64][BPAD]

    const int tid   = threadIdx.x;
    const int warp  = tid >> 5;
    const int lane  = tid & 31;
    const int g     = lane >> 2;
    const int tg    = lane & 3;
    const int gl    = lane >> 4;        // k-segment of ldsm lane
    const int mhalf = blockIdx.x & 1;
    const int pidx  = blockIdx.x >> 1;

    const int mw = (warp >> 1) * 32;    // warp M base within 256 (8 stripes)
    const int nw = (warp & 1) * 32;     // warp N base (2 stripes)

    const uint32_t As_base = (uint32_t)__cvta_generic_to_shared(As);
    const uint32_t Bs_base = (uint32_t)__cvta_generic_to_shared(Bs);

    // ---- load A once: g_W half -> swizzled SMEM (cp.async, 16B granules) ----
    {
        const __half* srcA = g_W + (size_t)(mhalf * MTILE) * MEM;
#pragma unroll
        for (int j = 0; j < 16; j++) {
            int i = tid + j * GT;                // 8192 granules
            int m = i >> 5, gs = i & 31;         // 32 granules per 512B row
            uint32_t sa = As_base + (uint32_t)(m * 512 + ((gs ^ (m & 7)) << 4));
            const __half* gp = srcA + m * MEM + gs * 8;
            asm volatile("cp.async.cg.shared.global [%0], [%1], 16;" :: "r"(sa), "l"(gp) : "memory");
        }
        asm volatile("cp.async.commit_group;" ::: "memory");
    }

    // A ldsm row bases (swizzle applied per-k at use)
    uint32_t a_row[2], am7[2];
#pragma unroll
    for (int mi = 0; mi < 2; mi++) {
        int m = mw + mi * 16 + (lane & 15);
        a_row[mi] = As_base + (uint32_t)(m * 512);
        am7[mi]   = (uint32_t)(m & 7);
    }
    // B ldsm lane offset (halfs), proven layout from prior rounds
    const int bgrp = lane >> 3;
    const uint32_t b_lane = (uint32_t)(((bgrp & 1) * 8 + (lane & 7)) * BPAD
                                       + nw + (bgrp >> 1) * 8);

    // ---- B staging: 64k x 64n fp32 = 1024 float4; 2 per thread ----
    const float4* membase = reinterpret_cast<const float4*>(memory);
    const int bk0 = tid >> 4,          bq0 = tid & 15;
    const int bk1 = (tid + 512) >> 4,  bq1 = (tid + 512) & 15;
    float4 br0, br1;

    auto ldg_B = [&](int c, int kc) {
        const float4* src = membase + (size_t)c * (NCHUNK / 4);
        br0 = __ldg(&src[(size_t)(kc * 64 + bk0) * (NCOL / 4) + bq0]);
        br1 = __ldg(&src[(size_t)(kc * 64 + bk1) * (NCOL / 4) + bq1]);
    };
    auto sts_B = [&](int buf) {
        __half2 h00 = __floats2half2_rn(br0.x, br0.y);
        __half2 h01 = __floats2half2_rn(br0.z, br0.w);
        __half2 h10 = __floats2half2_rn(br1.x, br1.y);
        __half2 h11 = __floats2half2_rn(br1.z, br1.w);
        uint2* d0 = reinterpret_cast<uint2*>(Bs + buf * B_BUF + bk0 * BPAD + bq0 * 4);
        uint2* d1 = reinterpret_cast<uint2*>(Bs + buf * B_BUF + bk1 * BPAD + bq1 * 4);
        *d0 = make_uint2(*reinterpret_cast<uint32_t*>(&h00), *reinterpret_cast<uint32_t*>(&h01));
        *d1 = make_uint2(*reinterpret_cast<uint32_t*>(&h10), *reinterpret_cast<uint32_t*>(&h11));
    };

    // ---- prologue ----
    const int nch = (NCHUNKS - pidx + pairs - 1) / pairs;   // chunks for this CTA
    int c = pidx;
    ldg_B(c, 0);
    asm volatile("cp.async.wait_group 0;" ::: "memory");    // A resident
    sts_B(0);
    __syncthreads();

    float d[2][4][4];
#pragma unroll
    for (int mi = 0; mi < 2; mi++)
#pragma unroll
        for (int ni = 0; ni < 4; ni++)
#pragma unroll
            for (int r = 0; r < 4; r++) d[mi][ni][r] = 0.f;

    // ---- persistent loop over chunks; flat B pipeline across boundaries ----
    for (int j = 0; j < nch; j++) {
        const int cnext = c + pairs;

#pragma unroll
        for (int kc = 0; kc < 4; kc++) {
            const bool more = !(j == nch - 1 && kc == 3);
            if (more)
                ldg_B((kc < 3) ? c : cnext, (kc + 1) & 3);

            const uint32_t bbase = Bs_base + ((kc & 1) * B_BUF + b_lane) * 2;
#pragma unroll
            for (int ks = 0; ks < 4; ks++) {
                uint32_t bf[8];
                ldsm_x4_t(bf,     bbase + ks * (16 * BPAD * 2));
                ldsm_x4_t(bf + 4, bbase + ks * (16 * BPAD * 2) + 32);
                const uint32_t gk = (uint32_t)(kc * 8 + ks * 2 + gl);
#pragma unroll
                for (int mi = 0; mi < 2; mi++) {
                    uint32_t a[4];
                    ldsm_x4(a, a_row[mi] + ((gk ^ am7[mi]) << 4));
                    mma16816(d[mi][0], a[0], a[1], a[2], a[3], bf[0], bf[1]);
                    mma16816(d[mi][1], a[0], a[1], a[2], a[3], bf[2], bf[3]);
                    mma16816(d[mi][2], a[0], a[1], a[2], a[3], bf[4], bf[5]);
                    mma16816(d[mi][3], a[0], a[1], a[2], a[3], bf[6], bf[7]);
                }
            }

            if (more) {
                sts_B((kc + 1) & 1);
                __syncthreads();
            }
        }

        // epilogue for chunk c: registers -> gmem (streaming), then reset
        const size_t cbase = (size_t)c * NCHUNK;
        const int mbase = mhalf * MTILE;
#pragma unroll
        for (int mi = 0; mi < 2; mi++) {
            const int r0 = mbase + mw + mi * 16 + g;
#pragma unroll
            for (int ni = 0; ni < 4; ni++) {
                const size_t col = cbase + nw + ni * 8 + tg * 2;
                stg_cs_v2(out + (size_t)r0 * NCOL + col,
                          make_float2(d[mi][ni][0], d[mi][ni][1]));
                stg_cs_v2(out + (size_t)(r0 + 8) * NCOL + col,
                          make_float2(d[mi][ni][2], d[mi][ni][3]));
#pragma unroll
                for (int r = 0; r < 4; r++) d[mi][ni][r] = 0.f;
            }
        }
        c = cnext;
    }
}

// ---------------------------------------------------------------------------
extern "C" void kernel_launch(void* const* d_in, const int* in_sizes, int n_in,
                              void* d_out, int out_size) {
    const float* features = (const float*)d_in[0];
    const float* keys     = (const float*)d_in[1];
    const float* memory   = (const float*)d_in[2];
    float*       out      = (float*)d_out;

    int sms = 148;
    cudaDeviceGetAttribute(&sms, cudaDevAttrMultiProcessorCount, 0);

    cudaFuncSetAttribute(gemm_kernel,
                         cudaFuncAttributeMaxDynamicSharedMemorySize, DYN_SMEM);

    topk_kernel<<<BATCH / 4, 256>>>(features, keys);
    gemm_kernel<<<2 * sms, GT, DYN_SMEM>>>(memory, out, sms);
}

// round 10
// speedup vs baseline: 1.0666x; 1.0666x over previous
#include <cuda_runtime.h>
#include <cuda_fp16.h>
#include <cstdint>

#define BATCH   512
#define MEM     256            // K dimension
#define FEAT    512
#define NCOL    131072         // 64*2048
#define TOPK    16

#define NCHUNK  128            // N columns per gemm work item
#define NCHUNKS (NCOL / NCHUNK)     // 1024
#define MTILE   256            // M rows per gemm CTA (one half)
#define GT      256            // gemm threads (8 warps)

#define BPAD    136            // halfs per B k-row in smem (128 + 8)
#define B_SLAB  (64 * BPAD)    // halfs per 64-K B slab (8704)
#define NSTAGE  5
#define A_HALFS (MTILE * MEM)  // 65536 halfs = 131072 B, swizzled, no pad
#define DYN_SMEM ((A_HALFS + NSTAGE * B_SLAB) * 2)   // 218112 bytes

// Dense fp16 weight matrix W[512][256] (built by prep kernel)
__device__ __align__(16) __half g_W[BATCH * MEM];
// fp16 copy of memory[256][131072] (built by prep kernel) — 64 MB scratch
__device__ __align__(16) __half g_memh[(size_t)MEM * NCOL];

// ---------------------------------------------------------------------------
// Kernel 1 (fused): blocks 0..127 do cosine sim + top-16 -> g_W;
// blocks 128.. convert memory fp32 -> fp16 into g_memh (grid-stride).
// ---------------------------------------------------------------------------
#define PREP_BLOCKS 2048

__global__ void __launch_bounds__(256)
prep_kernel(const float* __restrict__ features, const float* __restrict__ keys,
            const float* __restrict__ memory) {
    const int t = threadIdx.x;

    if (blockIdx.x >= 128) {
        // ---- convert path: 8 floats -> 8 halfs per iteration ----
        const float4* m4 = reinterpret_cast<const float4*>(memory);
        uint4* dst = reinterpret_cast<uint4*>(g_memh);
        const size_t total  = (size_t)MEM * NCOL / 8;   // 4,194,304
        const size_t stride = (size_t)(PREP_BLOCKS - 128) * 256;
        for (size_t i = (size_t)(blockIdx.x - 128) * 256 + t; i < total; i += stride) {
            float4 a = m4[2 * i];
            float4 b = m4[2 * i + 1];
            __half2 h0 = __floats2half2_rn(a.x, a.y);
            __half2 h1 = __floats2half2_rn(a.z, a.w);
            __half2 h2 = __floats2half2_rn(b.x, b.y);
            __half2 h3 = __floats2half2_rn(b.z, b.w);
            uint4 pk;
            pk.x = *reinterpret_cast<uint32_t*>(&h0);
            pk.y = *reinterpret_cast<uint32_t*>(&h1);
            pk.z = *reinterpret_cast<uint32_t*>(&h2);
            pk.w = *reinterpret_cast<uint32_t*>(&h3);
            dst[i] = pk;
        }
        return;
    }

    // ---- topk path (proven since R4) ----
    __shared__ float f_s[4 * FEAT];
    __shared__ float fn_s[4];
    __shared__ float sim_s[4 * 264];
    __shared__ float topv_s[4][TOPK];
    __shared__ int   topi_s[4][TOPK];
    __shared__ float w_dense[4][MEM];

    const int warp = t >> 5;
    const int lane = t & 31;
    const int base = blockIdx.x * 4;

    float4* f4s = reinterpret_cast<float4*>(f_s);
    const float4* fg = reinterpret_cast<const float4*>(features) + (size_t)base * (FEAT / 4);
    for (int i = t; i < 4 * FEAT / 4; i += 256) f4s[i] = fg[i];
    __syncthreads();

    if (warp < 4) {
        float s = 0.f;
#pragma unroll
        for (int m = 0; m < FEAT / 32; m++) {
            float v = f_s[warp * FEAT + lane + m * 32];
            s += v * v;
        }
#pragma unroll
        for (int off = 16; off; off >>= 1) s += __shfl_down_sync(0xffffffffu, s, off);
        if (lane == 0) fn_s[warp] = fmaxf(sqrtf(s), 1e-8f);
    }
    __syncthreads();

    const float4* krow = reinterpret_cast<const float4*>(keys) + (size_t)t * (FEAT / 4);
    float acc[4] = {0.f, 0.f, 0.f, 0.f};
    float kn = 0.f;
#pragma unroll 4
    for (int dd = 0; dd < FEAT / 4; dd++) {
        float4 kv = krow[dd];
        kn += kv.x * kv.x + kv.y * kv.y + kv.z * kv.z + kv.w * kv.w;
#pragma unroll
        for (int b = 0; b < 4; b++) {
            float4 fv = f4s[b * (FEAT / 4) + dd];
            acc[b] += kv.x * fv.x + kv.y * fv.y + kv.z * fv.z + kv.w * fv.w;
        }
    }
    const float rkn = fmaxf(sqrtf(kn), 1e-8f);
#pragma unroll
    for (int b = 0; b < 4; b++)
        sim_s[b * 264 + t] = acc[b] / (fn_s[b] * rkn);

#pragma unroll
    for (int r = 0; r < 4; r++) w_dense[r][t] = 0.f;
    __syncthreads();

    if (warp < 4) {
        float v[8];
#pragma unroll
        for (int m = 0; m < 8; m++) v[m] = sim_s[warp * 264 + lane * 8 + m];

        for (int k = 0; k < TOPK; k++) {
            float best = v[0];
            int bm = 0;
#pragma unroll
            for (int m = 1; m < 8; m++)
                if (v[m] > best) { best = v[m]; bm = m; }
            int gi = lane * 8 + bm;
#pragma unroll
            for (int off = 16; off; off >>= 1) {
                float ov = __shfl_down_sync(0xffffffffu, best, off);
                int   oi = __shfl_down_sync(0xffffffffu, gi,   off);
                if (ov > best || (ov == best && oi < gi)) { best = ov; gi = oi; }
            }
            best = __shfl_sync(0xffffffffu, best, 0);
            gi   = __shfl_sync(0xffffffffu, gi,   0);
            if (lane == (gi >> 3)) {
                int li = gi & 7;
#pragma unroll
                for (int m = 0; m < 8; m++)
                    if (m == li) v[m] = -3.0e38f;
            }
            if (lane == 0) { topv_s[warp][k] = best; topi_s[warp][k] = gi; }
        }
        __syncwarp();

        float tv = (lane < TOPK) ? fmaxf(topv_s[warp][lane], 0.f) : 0.f;
        float s = tv;
#pragma unroll
        for (int off = 16; off; off >>= 1) s += __shfl_down_sync(0xffffffffu, s, off);
        s = __shfl_sync(0xffffffffu, s, 0);
        const float inv = 1.0f / s;
        if (lane < TOPK)
            w_dense[warp][topi_s[warp][lane]] = tv * inv;
    }
    __syncthreads();

#pragma unroll
    for (int r = 0; r < 4; r++)
        g_W[(base + r) * MEM + t] = __float2half_rn(w_dense[r][t]);
}

// ---------------------------------------------------------------------------
// Kernel 2: persistent HMMA GEMM, 8 warps, warp tile 64M x 64N.
// A (256x256 W half) loaded once (XOR-swizzled). B slabs (64K x 128N fp16)
// flow through a 5-stage cp.async ring; one barrier per slab. CTA pairs
// (2p,2p+1) walk identical chunk lists => B's second read hits L2.
// ---------------------------------------------------------------------------
__device__ __forceinline__ void mma16816(float d[4],
                                         uint32_t a0, uint32_t a1, uint32_t a2, uint32_t a3,
                                         uint32_t b0, uint32_t b1) {
    asm volatile(
        "mma.sync.aligned.m16n8k16.row.col.f32.f16.f16.f32 "
        "{%0,%1,%2,%3}, {%4,%5,%6,%7}, {%8,%9}, {%0,%1,%2,%3};"
        : "+f"(d[0]), "+f"(d[1]), "+f"(d[2]), "+f"(d[3])
        : "r"(a0), "r"(a1), "r"(a2), "r"(a3), "r"(b0), "r"(b1));
}
__device__ __forceinline__ void ldsm_x4(uint32_t r[4], uint32_t sa) {
    asm volatile("ldmatrix.sync.aligned.m8n8.x4.shared.b16 {%0,%1,%2,%3}, [%4];"
        : "=r"(r[0]), "=r"(r[1]), "=r"(r[2]), "=r"(r[3]) : "r"(sa));
}
__device__ __forceinline__ void ldsm_x4_t(uint32_t r[4], uint32_t sa) {
    asm volatile("ldmatrix.sync.aligned.m8n8.x4.trans.shared.b16 {%0,%1,%2,%3}, [%4];"
        : "=r"(r[0]), "=r"(r[1]), "=r"(r[2]), "=r"(r[3]) : "r"(sa));
}
__device__ __forceinline__ void stg_cs_v2(float* p, float2 v) {
    asm volatile("st.global.cs.v2.f32 [%0], {%1, %2};" :: "l"(p), "f"(v.x), "f"(v.y) : "memory");
}

__global__ void __launch_bounds__(GT, 1)
gemm_kernel(float* __restrict__ out, int pairs) {
    extern __shared__ __half sm[];
    __half* As = sm;                    // [256][256] swizzled (no pad)
    __half* Bs = sm + A_HALFS;          // [NSTAGE][64][BPAD]

    const int tid   = threadIdx.x;
    const int warp  = tid >> 5;
    const int lane  = tid & 31;
    const int g     = lane >> 2;
    const int tg    = lane & 3;
    const int gl    = lane >> 4;
    const int mhalf = blockIdx.x & 1;
    const int pidx  = blockIdx.x >> 1;

    const int mw = (warp >> 1) * 64;    // 4 M stripes of 64
    const int nw = (warp & 1) * 64;     // 2 N stripes of 64

    const uint32_t As_base = (uint32_t)__cvta_generic_to_shared(As);
    const uint32_t Bs_base = (uint32_t)__cvta_generic_to_shared(Bs);

    // ---- load A once (group 0) ----
    {
        const __half* srcA = g_W + (size_t)(mhalf * MTILE) * MEM;
#pragma unroll
        for (int j = 0; j < 32; j++) {
            int i = tid + j * GT;                // 8192 granules of 16B
            int m = i >> 5, gs = i & 31;
            uint32_t sa = As_base + (uint32_t)(m * 512 + ((gs ^ (m & 7)) << 4));
            const __half* gp = srcA + m * MEM + gs * 8;
            asm volatile("cp.async.cg.shared.global [%0], [%1], 16;" :: "r"(sa), "l"(gp) : "memory");
        }
        asm volatile("cp.async.commit_group;" ::: "memory");
    }

    const int nch   = (NCHUNKS - pidx + pairs - 1) / pairs;
    const int total = nch * 4;           // 64-K slabs for this CTA

    auto issue_slab = [&](int tt) {
        const int c  = pidx + (tt >> 2) * pairs;
        const int kc = tt & 3;
        const __half* src = g_memh + (size_t)(kc * 64) * NCOL + (size_t)c * NCHUNK;
        const uint32_t dstb = Bs_base + (uint32_t)((tt % NSTAGE) * B_SLAB * 2);
#pragma unroll
        for (int q = 0; q < 4; q++) {
            int i = tid + q * GT;                // 1024 granules of 16B
            int r = i >> 4, seg = i & 15;
            uint32_t sa = dstb + (uint32_t)(r * (BPAD * 2) + seg * 16);
            const __half* gp = src + (size_t)r * NCOL + seg * 8;
            asm volatile("cp.async.cg.shared.global [%0], [%1], 16;" :: "r"(sa), "l"(gp) : "memory");
        }
        asm volatile("cp.async.commit_group;" ::: "memory");
    };

    issue_slab(0);
    issue_slab(1);
    issue_slab(2);

    // A fragment row bases (swizzle applied per-k at use)
    uint32_t a_row[4], am7[4];
#pragma unroll
    for (int mi = 0; mi < 4; mi++) {
        int m = mw + mi * 16 + (lane & 15);
        a_row[mi] = As_base + (uint32_t)(m * 512);
        am7[mi]   = (uint32_t)(m & 7);
    }
    // B ldmatrix lane offset (bytes within a slab); proven layout
    const int bgrp = lane >> 3;
    const uint32_t b_lane_off =
        (uint32_t)(((bgrp & 1) * 8 + (lane & 7)) * (BPAD * 2) + (nw + (bgrp >> 1) * 8) * 2);

    float d[4][8][4];
#pragma unroll
    for (int mi = 0; mi < 4; mi++)
#pragma unroll
        for (int ni = 0; ni < 8; ni++)
#pragma unroll
            for (int r = 0; r < 4; r++) d[mi][ni][r] = 0.f;

    int c = pidx;
    for (int t = 0; t < total; t++) {
        if (t + 3 < total) issue_slab(t + 3);

        const int rem = total - 1 - t;
        if (rem >= 3)      asm volatile("cp.async.wait_group 3;" ::: "memory");
        else if (rem == 2) asm volatile("cp.async.wait_group 2;" ::: "memory");
        else if (rem == 1) asm volatile("cp.async.wait_group 1;" ::: "memory");
        else               asm volatile("cp.async.wait_group 0;" ::: "memory");
        __syncthreads();

        const int kc = t & 3;
        const uint32_t bbase = Bs_base + (uint32_t)((t % NSTAGE) * B_SLAB * 2) + b_lane_off;

#pragma unroll
        for (int ks = 0; ks < 4; ks++) {
            uint32_t bf[16];
#pragma unroll
            for (int j = 0; j < 4; j++)
                ldsm_x4_t(bf + 4 * j, bbase + ks * (16 * BPAD * 2) + j * 32);
            const uint32_t gk = (uint32_t)(kc * 8 + ks * 2 + gl);
#pragma unroll
            for (int mi = 0; mi < 4; mi++) {
                uint32_t a[4];
                ldsm_x4(a, a_row[mi] + ((gk ^ am7[mi]) << 4));
#pragma unroll
                for (int j = 0; j < 4; j++) {
                    mma16816(d[mi][2 * j],     a[0], a[1], a[2], a[3], bf[4 * j],     bf[4 * j + 1]);
                    mma16816(d[mi][2 * j + 1], a[0], a[1], a[2], a[3], bf[4 * j + 2], bf[4 * j + 3]);
                }
            }
        }

        if (kc == 3) {
            // epilogue for chunk c: streaming stores, then reset accumulators
            const size_t cbase = (size_t)c * NCHUNK;
            const int mbase = mhalf * MTILE;
#pragma unroll
            for (int mi = 0; mi < 4; mi++) {
                const int r0 = mbase + mw + mi * 16 + g;
#pragma unroll
                for (int ni = 0; ni < 8; ni++) {
                    const size_t col = cbase + nw + ni * 8 + tg * 2;
                    stg_cs_v2(out + (size_t)r0 * NCOL + col,
                              make_float2(d[mi][ni][0], d[mi][ni][1]));
                    stg_cs_v2(out + (size_t)(r0 + 8) * NCOL + col,
                              make_float2(d[mi][ni][2], d[mi][ni][3]));
#pragma unroll
                    for (int r = 0; r < 4; r++) d[mi][ni][r] = 0.f;
                }
            }
            c += pairs;
        }
    }
}

// ---------------------------------------------------------------------------
extern "C" void kernel_launch(void* const* d_in, const int* in_sizes, int n_in,
                              void* d_out, int out_size) {
    const float* features = (const float*)d_in[0];
    const float* keys     = (const float*)d_in[1];
    const float* memory   = (const float*)d_in[2];
    float*       out      = (float*)d_out;

    int sms = 148;
    cudaDeviceGetAttribute(&sms, cudaDevAttrMultiProcessorCount, 0);

    cudaFuncSetAttribute(gemm_kernel,
                         cudaFuncAttributeMaxDynamicSharedMemorySize, DYN_SMEM);

    prep_kernel<<<PREP_BLOCKS, 256>>>(features, keys, memory);
    gemm_kernel<<<2 * sms, GT, DYN_SMEM>>>(out, sms);
}

// round 11
// speedup vs baseline: 1.1010x; 1.0322x over previous
#include <cuda_runtime.h>
#include <cuda_fp16.h>
#include <cstdint>

#define BATCH   512
#define MEM     256            // K dimension
#define FEAT    512
#define NCOL    131072         // 64*2048
#define TOPK    16

#define NCHUNK  128            // N columns per gemm work item
#define NCHUNKS (NCOL / NCHUNK)     // 1024
#define MTILE   256            // M rows per gemm CTA (one half)
#define GT      256            // gemm threads (8 warps)

#define BPAD    136            // halfs per B k-row in smem (128 + 8)
#define B_SLAB  (64 * BPAD)    // halfs per 64-K fp16 B slab (8704)
#define A_HALFS (MTILE * MEM)  // 65536 halfs = 131072 B, swizzled, no pad
#define DYN_SMEM ((A_HALFS + 2 * B_SLAB) * 2)   // 165888 bytes

// Dense fp16 weight matrix W[512][256] (built by topk kernel)
__device__ __align__(16) __half g_W[BATCH * MEM];

// ---------------------------------------------------------------------------
// Kernel 1: cosine sim + top-16 + clamp + renormalize -> dense fp16 W.
// (proven since R4)
// ---------------------------------------------------------------------------
__global__ void __launch_bounds__(256)
topk_kernel(const float* __restrict__ features, const float* __restrict__ keys) {
    __shared__ float f_s[4 * FEAT];
    __shared__ float fn_s[4];
    __shared__ float sim_s[4 * 264];
    __shared__ float topv_s[4][TOPK];
    __shared__ int   topi_s[4][TOPK];
    __shared__ float w_dense[4][MEM];

    const int t    = threadIdx.x;
    const int warp = t >> 5;
    const int lane = t & 31;
    const int base = blockIdx.x * 4;

    float4* f4s = reinterpret_cast<float4*>(f_s);
    const float4* fg = reinterpret_cast<const float4*>(features) + (size_t)base * (FEAT / 4);
    for (int i = t; i < 4 * FEAT / 4; i += 256) f4s[i] = fg[i];
    __syncthreads();

    if (warp < 4) {
        float s = 0.f;
#pragma unroll
        for (int m = 0; m < FEAT / 32; m++) {
            float v = f_s[warp * FEAT + lane + m * 32];
            s += v * v;
        }
#pragma unroll
        for (int off = 16; off; off >>= 1) s += __shfl_down_sync(0xffffffffu, s, off);
        if (lane == 0) fn_s[warp] = fmaxf(sqrtf(s), 1e-8f);
    }
    __syncthreads();

    const float4* krow = reinterpret_cast<const float4*>(keys) + (size_t)t * (FEAT / 4);
    float acc[4] = {0.f, 0.f, 0.f, 0.f};
    float kn = 0.f;
#pragma unroll 4
    for (int dd = 0; dd < FEAT / 4; dd++) {
        float4 kv = krow[dd];
        kn += kv.x * kv.x + kv.y * kv.y + kv.z * kv.z + kv.w * kv.w;
#pragma unroll
        for (int b = 0; b < 4; b++) {
            float4 fv = f4s[b * (FEAT / 4) + dd];
            acc[b] += kv.x * fv.x + kv.y * fv.y + kv.z * fv.z + kv.w * fv.w;
        }
    }
    const float rkn = fmaxf(sqrtf(kn), 1e-8f);
#pragma unroll
    for (int b = 0; b < 4; b++)
        sim_s[b * 264 + t] = acc[b] / (fn_s[b] * rkn);

#pragma unroll
    for (int r = 0; r < 4; r++) w_dense[r][t] = 0.f;
    __syncthreads();

    if (warp < 4) {
        float v[8];
#pragma unroll
        for (int m = 0; m < 8; m++) v[m] = sim_s[warp * 264 + lane * 8 + m];

        for (int k = 0; k < TOPK; k++) {
            float best = v[0];
            int bm = 0;
#pragma unroll
            for (int m = 1; m < 8; m++)
                if (v[m] > best) { best = v[m]; bm = m; }
            int gi = lane * 8 + bm;
#pragma unroll
            for (int off = 16; off; off >>= 1) {
                float ov = __shfl_down_sync(0xffffffffu, best, off);
                int   oi = __shfl_down_sync(0xffffffffu, gi,   off);
                if (ov > best || (ov == best && oi < gi)) { best = ov; gi = oi; }
            }
            best = __shfl_sync(0xffffffffu, best, 0);
            gi   = __shfl_sync(0xffffffffu, gi,   0);
            if (lane == (gi >> 3)) {
                int li = gi & 7;
#pragma unroll
                for (int m = 0; m < 8; m++)
                    if (m == li) v[m] = -3.0e38f;
            }
            if (lane == 0) { topv_s[warp][k] = best; topi_s[warp][k] = gi; }
        }
        __syncwarp();

        float tv = (lane < TOPK) ? fmaxf(topv_s[warp][lane], 0.f) : 0.f;
        float s = tv;
#pragma unroll
        for (int off = 16; off; off >>= 1) s += __shfl_down_sync(0xffffffffu, s, off);
        s = __shfl_sync(0xffffffffu, s, 0);
        const float inv = 1.0f / s;
        if (lane < TOPK)
            w_dense[warp][topi_s[warp][lane]] = tv * inv;
    }
    __syncthreads();

#pragma unroll
    for (int r = 0; r < 4; r++)
        g_W[(base + r) * MEM + t] = __float2half_rn(w_dense[r][t]);
}

// ---------------------------------------------------------------------------
// Kernel 2: persistent HMMA GEMM, 8 warps, warp tile 64M x 64N.
// A (256x256 W half) loaded once (XOR-swizzled, cp.async). B slabs
// (64K x 128N) fetched as fp32 LDG one slab ahead in two 4-float4 register
// waves interleaved with the mma stream, cvt'd to a 2-deep fp16 slab ring.
// CTA pairs (2p,2p+1) walk identical chunk lists => B's 2nd read hits L2.
// ---------------------------------------------------------------------------
__device__ __forceinline__ void mma16816(float d[4],
                                         uint32_t a0, uint32_t a1, uint32_t a2, uint32_t a3,
                                         uint32_t b0, uint32_t b1) {
    asm volatile(
        "mma.sync.aligned.m16n8k16.row.col.f32.f16.f16.f32 "
        "{%0,%1,%2,%3}, {%4,%5,%6,%7}, {%8,%9}, {%0,%1,%2,%3};"
        : "+f"(d[0]), "+f"(d[1]), "+f"(d[2]), "+f"(d[3])
        : "r"(a0), "r"(a1), "r"(a2), "r"(a3), "r"(b0), "r"(b1));
}
__device__ __forceinline__ void ldsm_x4(uint32_t r[4], uint32_t sa) {
    asm volatile("ldmatrix.sync.aligned.m8n8.x4.shared.b16 {%0,%1,%2,%3}, [%4];"
        : "=r"(r[0]), "=r"(r[1]), "=r"(r[2]), "=r"(r[3]) : "r"(sa));
}
__device__ __forceinline__ void ldsm_x4_t(uint32_t r[4], uint32_t sa) {
    asm volatile("ldmatrix.sync.aligned.m8n8.x4.trans.shared.b16 {%0,%1,%2,%3}, [%4];"
        : "=r"(r[0]), "=r"(r[1]), "=r"(r[2]), "=r"(r[3]) : "r"(sa));
}
__device__ __forceinline__ void stg_cs_v2(float* p, float2 v) {
    asm volatile("st.global.cs.v2.f32 [%0], {%1, %2};" :: "l"(p), "f"(v.x), "f"(v.y) : "memory");
}

__global__ void __launch_bounds__(GT, 1)
gemm_kernel(const float* __restrict__ memory, float* __restrict__ out, int pairs) {
    extern __shared__ __half sm[];
    __half* As = sm;                    // [256][256] swizzled (no pad)
    __half* Bs = sm + A_HALFS;          // [2][64][BPAD]

    const int tid   = threadIdx.x;
    const int warp  = tid >> 5;
    const int lane  = tid & 31;
    const int g     = lane >> 2;
    const int tg    = lane & 3;
    const int gl    = lane >> 4;
    const int mhalf = blockIdx.x & 1;
    const int pidx  = blockIdx.x >> 1;

    const int mw = (warp >> 1) * 64;    // 4 M stripes of 64
    const int nw = (warp & 1) * 64;     // 2 N stripes of 64

    const uint32_t As_base = (uint32_t)__cvta_generic_to_shared(As);
    const uint32_t Bs_base = (uint32_t)__cvta_generic_to_shared(Bs);

    // ---- load A once (cp.async, XOR-swizzled) ----
    {
        const __half* srcA = g_W + (size_t)(mhalf * MTILE) * MEM;
#pragma unroll
        for (int j = 0; j < 32; j++) {
            int i = tid + j * GT;                // 8192 granules of 16B
            int m = i >> 5, gs = i & 31;
            uint32_t sa = As_base + (uint32_t)(m * 512 + ((gs ^ (m & 7)) << 4));
            const __half* gp = srcA + m * MEM + gs * 8;
            asm volatile("cp.async.cg.shared.global [%0], [%1], 16;" :: "r"(sa), "l"(gp) : "memory");
        }
        asm volatile("cp.async.commit_group;" ::: "memory");
    }

    const int nch   = (NCHUNKS - pidx + pairs - 1) / pairs;
    const int total = nch * 4;           // 64-K slabs for this CTA

    // ---- B staging: slab = 64 rows x 128 cols fp32 = 2048 float4 ----
    // thread covers granules tid + q*GT; half0 = q 0..3 (rows 0..31),
    // half1 = q 4..7 (rows 32..63).
    const float4* membase = reinterpret_cast<const float4*>(memory);
    float4 br[4];

    auto ldg_half = [&](int tt, int h) {
        const int c  = pidx + (tt >> 2) * pairs;
        const int kc = tt & 3;
        const float4* src = membase + (size_t)(kc * 64) * (NCOL / 4) + (size_t)c * 32;
#pragma unroll
        for (int q = 0; q < 4; q++) {
            int i = tid + (q + 4 * h) * GT;
            br[q] = __ldg(&src[(size_t)(i >> 5) * (NCOL / 4) + (i & 31)]);
        }
    };
    auto sts_half = [&](int tt, int h) {
        const int buf = tt & 1;
#pragma unroll
        for (int q = 0; q < 4; q++) {
            int i = tid + (q + 4 * h) * GT;
            int r = i >> 5, c4 = i & 31;
            __half2 h0 = __floats2half2_rn(br[q].x, br[q].y);
            __half2 h1 = __floats2half2_rn(br[q].z, br[q].w);
            uint2* dp = reinterpret_cast<uint2*>(Bs + buf * B_SLAB + r * BPAD + c4 * 4);
            *dp = make_uint2(*reinterpret_cast<uint32_t*>(&h0),
                             *reinterpret_cast<uint32_t*>(&h1));
        }
    };

    // ---- prologue: stage slab 0, wait for A ----
    ldg_half(0, 0); sts_half(0, 0);
    ldg_half(0, 1); sts_half(0, 1);
    asm volatile("cp.async.wait_group 0;" ::: "memory");
    __syncthreads();

    // A fragment row bases (swizzle applied per-k at use)
    uint32_t a_row[4], am7[4];
#pragma unroll
    for (int mi = 0; mi < 4; mi++) {
        int m = mw + mi * 16 + (lane & 15);
        a_row[mi] = As_base + (uint32_t)(m * 512);
        am7[mi]   = (uint32_t)(m & 7);
    }
    // B ldmatrix lane offset (bytes within a slab)
    const int bgrp = lane >> 3;
    const uint32_t b_lane_off =
        (uint32_t)(((bgrp & 1) * 8 + (lane & 7)) * (BPAD * 2) + (nw + (bgrp >> 1) * 8) * 2);

    float d[4][8][4];
#pragma unroll
    for (int mi = 0; mi < 4; mi++)
#pragma unroll
        for (int ni = 0; ni < 8; ni++)
#pragma unroll
            for (int r = 0; r < 4; r++) d[mi][ni][r] = 0.f;

    int c = pidx;
    for (int t = 0; t < total; t++) {
        const int  kc   = t & 3;
        const bool more = (t + 1 < total);
        const uint32_t bbase = Bs_base + (uint32_t)((t & 1) * B_SLAB * 2) + b_lane_off;

#pragma unroll
        for (int ks = 0; ks < 4; ks++) {
            // interleave next-slab staging with the mma stream
            if (ks == 0 && more) ldg_half(t + 1, 0);
            if (ks == 1 && more) { sts_half(t + 1, 0); ldg_half(t + 1, 1); }
            if (ks == 3 && more) sts_half(t + 1, 1);

            uint32_t bf[16];
#pragma unroll
            for (int j = 0; j < 4; j++)
                ldsm_x4_t(bf + 4 * j, bbase + ks * (16 * BPAD * 2) + j * 32);
            const uint32_t gk = (uint32_t)(kc * 8 + ks * 2 + gl);
#pragma unroll
            for (int mi = 0; mi < 4; mi++) {
                uint32_t a[4];
                ldsm_x4(a, a_row[mi] + ((gk ^ am7[mi]) << 4));
#pragma unroll
                for (int j = 0; j < 4; j++) {
                    mma16816(d[mi][2 * j],     a[0], a[1], a[2], a[3], bf[4 * j],     bf[4 * j + 1]);
                    mma16816(d[mi][2 * j + 1], a[0], a[1], a[2], a[3], bf[4 * j + 2], bf[4 * j + 3]);
                }
            }
        }

        if (kc == 3) {
            // epilogue for chunk c: streaming stores, reset accumulators
            const size_t cbase = (size_t)c * NCHUNK;
            const int mbase = mhalf * MTILE;
#pragma unroll
            for (int mi = 0; mi < 4; mi++) {
                const int r0 = mbase + mw + mi * 16 + g;
#pragma unroll
                for (int ni = 0; ni < 8; ni++) {
                    const size_t col = cbase + nw + ni * 8 + tg * 2;
                    stg_cs_v2(out + (size_t)r0 * NCOL + col,
                              make_float2(d[mi][ni][0], d[mi][ni][1]));
                    stg_cs_v2(out + (size_t)(r0 + 8) * NCOL + col,
                              make_float2(d[mi][ni][2], d[mi][ni][3]));
#pragma unroll
                    for (int r = 0; r < 4; r++) d[mi][ni][r] = 0.f;
                }
            }
            c += pairs;
        }

        __syncthreads();   // next slab's fp16 buffer fully written
    }
}

// ---------------------------------------------------------------------------
extern "C" void kernel_launch(void* const* d_in, const int* in_sizes, int n_in,
                              void* d_out, int out_size) {
    const float* features = (const float*)d_in[0];
    const float* keys     = (const float*)d_in[1];
    const float* memory   = (const float*)d_in[2];
    float*       out      = (float*)d_out;

    int sms = 148;
    cudaDeviceGetAttribute(&sms, cudaDevAttrMultiProcessorCount, 0);

    cudaFuncSetAttribute(gemm_kernel,
                         cudaFuncAttributeMaxDynamicSharedMemorySize, DYN_SMEM);

    topk_kernel<<<BATCH / 4, 256>>>(features, keys);
    gemm_kernel<<<2 * sms, GT, DYN_SMEM>>>(memory, out, sms);
}

// round 12
// speedup vs baseline: 1.2574x; 1.1420x over previous
#include <cuda_runtime.h>
#include <cuda_fp16.h>
#include <cstdint>

#define BATCH   512
#define MEM     256            // K dimension
#define FEAT    512
#define NCOL    131072         // 64*2048
#define TOPK    16

#define NCHUNK  128            // N columns per gemm work item
#define NCHUNKS (NCOL / NCHUNK)     // 1024
#define MTILE   256            // M rows per gemm CTA (one half)
#define GT      256            // gemm threads (8 warps)

#define BPAD    136            // halfs per B k-row in smem (128 + 8)
#define B_SLAB  (64 * BPAD)    // halfs per 64-K fp16 B slab (8704)
#define A_HALFS (MTILE * MEM)  // 65536 halfs = 131072 B, swizzled, no pad
#define DYN_SMEM ((A_HALFS + 2 * B_SLAB) * 2)   // 165888 bytes

// Dense fp16 weight matrix W[512][256] (built by topk kernel)
__device__ __align__(16) __half g_W[BATCH * MEM];

// ---------------------------------------------------------------------------
// Kernel 1: cosine sim + top-16 + clamp + renormalize -> dense fp16 W.
// (proven since R4)
// ---------------------------------------------------------------------------
__global__ void __launch_bounds__(256)
topk_kernel(const float* __restrict__ features, const float* __restrict__ keys) {
    __shared__ float f_s[4 * FEAT];
    __shared__ float fn_s[4];
    __shared__ float sim_s[4 * 264];
    __shared__ float topv_s[4][TOPK];
    __shared__ int   topi_s[4][TOPK];
    __shared__ float w_dense[4][MEM];

    const int t    = threadIdx.x;
    const int warp = t >> 5;
    const int lane = t & 31;
    const int base = blockIdx.x * 4;

    float4* f4s = reinterpret_cast<float4*>(f_s);
    const float4* fg = reinterpret_cast<const float4*>(features) + (size_t)base * (FEAT / 4);
    for (int i = t; i < 4 * FEAT / 4; i += 256) f4s[i] = fg[i];
    __syncthreads();

    if (warp < 4) {
        float s = 0.f;
#pragma unroll
        for (int m = 0; m < FEAT / 32; m++) {
            float v = f_s[warp * FEAT + lane + m * 32];
            s += v * v;
        }
#pragma unroll
        for (int off = 16; off; off >>= 1) s += __shfl_down_sync(0xffffffffu, s, off);
        if (lane == 0) fn_s[warp] = fmaxf(sqrtf(s), 1e-8f);
    }
    __syncthreads();

    const float4* krow = reinterpret_cast<const float4*>(keys) + (size_t)t * (FEAT / 4);
    float acc[4] = {0.f, 0.f, 0.f, 0.f};
    float kn = 0.f;
#pragma unroll 4
    for (int dd = 0; dd < FEAT / 4; dd++) {
        float4 kv = krow[dd];
        kn += kv.x * kv.x + kv.y * kv.y + kv.z * kv.z + kv.w * kv.w;
#pragma unroll
        for (int b = 0; b < 4; b++) {
            float4 fv = f4s[b * (FEAT / 4) + dd];
            acc[b] += kv.x * fv.x + kv.y * fv.y + kv.z * fv.z + kv.w * fv.w;
        }
    }
    const float rkn = fmaxf(sqrtf(kn), 1e-8f);
#pragma unroll
    for (int b = 0; b < 4; b++)
        sim_s[b * 264 + t] = acc[b] / (fn_s[b] * rkn);

#pragma unroll
    for (int r = 0; r < 4; r++) w_dense[r][t] = 0.f;
    __syncthreads();

    if (warp < 4) {
        float v[8];
#pragma unroll
        for (int m = 0; m < 8; m++) v[m] = sim_s[warp * 264 + lane * 8 + m];

        for (int k = 0; k < TOPK; k++) {
            float best = v[0];
            int bm = 0;
#pragma unroll
            for (int m = 1; m < 8; m++)
                if (v[m] > best) { best = v[m]; bm = m; }
            int gi = lane * 8 + bm;
#pragma unroll
            for (int off = 16; off; off >>= 1) {
                float ov = __shfl_down_sync(0xffffffffu, best, off);
                int   oi = __shfl_down_sync(0xffffffffu, gi,   off);
                if (ov > best || (ov == best && oi < gi)) { best = ov; gi = oi; }
            }
            best = __shfl_sync(0xffffffffu, best, 0);
            gi   = __shfl_sync(0xffffffffu, gi,   0);
            if (lane == (gi >> 3)) {
                int li = gi & 7;
#pragma unroll
                for (int m = 0; m < 8; m++)
                    if (m == li) v[m] = -3.0e38f;
            }
            if (lane == 0) { topv_s[warp][k] = best; topi_s[warp][k] = gi; }
        }
        __syncwarp();

        float tv = (lane < TOPK) ? fmaxf(topv_s[warp][lane], 0.f) : 0.f;
        float s = tv;
#pragma unroll
        for (int off = 16; off; off >>= 1) s += __shfl_down_sync(0xffffffffu, s, off);
        s = __shfl_sync(0xffffffffu, s, 0);
        const float inv = 1.0f / s;
        if (lane < TOPK)
            w_dense[warp][topi_s[warp][lane]] = tv * inv;
    }
    __syncthreads();

#pragma unroll
    for (int r = 0; r < 4; r++)
        g_W[(base + r) * MEM + t] = __float2half_rn(w_dense[r][t]);
}

// ---------------------------------------------------------------------------
// Kernel 2: persistent HMMA GEMM, 8 warps, warp tile 64M x 64N.
// A (256x256 W half) loaded once (XOR-swizzled, cp.async).
// B slabs (64K x 128N fp32) staged via registers with a 2-ks (~900cyc)
// LDG->STS window + L2 prefetch 3 slabs ahead; cvt to 2-deep fp16 ring.
// CTA pairs (2p,2p+1) walk identical chunk lists => B's 2nd read hits L2.
// ---------------------------------------------------------------------------
__device__ __forceinline__ void mma16816(float d[4],
                                         uint32_t a0, uint32_t a1, uint32_t a2, uint32_t a3,
                                         uint32_t b0, uint32_t b1) {
    asm volatile(
        "mma.sync.aligned.m16n8k16.row.col.f32.f16.f16.f32 "
        "{%0,%1,%2,%3}, {%4,%5,%6,%7}, {%8,%9}, {%0,%1,%2,%3};"
        : "+f"(d[0]), "+f"(d[1]), "+f"(d[2]), "+f"(d[3])
        : "r"(a0), "r"(a1), "r"(a2), "r"(a3), "r"(b0), "r"(b1));
}
__device__ __forceinline__ void ldsm_x4(uint32_t r[4], uint32_t sa) {
    asm volatile("ldmatrix.sync.aligned.m8n8.x4.shared.b16 {%0,%1,%2,%3}, [%4];"
        : "=r"(r[0]), "=r"(r[1]), "=r"(r[2]), "=r"(r[3]) : "r"(sa));
}
__device__ __forceinline__ void ldsm_x4_t(uint32_t r[4], uint32_t sa) {
    asm volatile("ldmatrix.sync.aligned.m8n8.x4.trans.shared.b16 {%0,%1,%2,%3}, [%4];"
        : "=r"(r[0]), "=r"(r[1]), "=r"(r[2]), "=r"(r[3]) : "r"(sa));
}
__device__ __forceinline__ void stg_cs_v2(float* p, float2 v) {
    asm volatile("st.global.cs.v2.f32 [%0], {%1, %2};" :: "l"(p), "f"(v.x), "f"(v.y) : "memory");
}
__device__ __forceinline__ void prefetch_l2(const void* p) {
    asm volatile("prefetch.global.L2 [%0];" :: "l"(p));
}

__global__ void __launch_bounds__(GT, 1)
gemm_kernel(const float* __restrict__ memory, float* __restrict__ out, int pairs) {
    extern __shared__ __half sm[];
    __half* As = sm;                    // [256][256] swizzled (no pad)
    __half* Bs = sm + A_HALFS;          // [2][64][BPAD]

    const int tid   = threadIdx.x;
    const int warp  = tid >> 5;
    const int lane  = tid & 31;
    const int g     = lane >> 2;
    const int tg    = lane & 3;
    const int gl    = lane >> 4;
    const int mhalf = blockIdx.x & 1;
    const int pidx  = blockIdx.x >> 1;

    const int mw = (warp >> 1) * 64;    // 4 M stripes of 64
    const int nw = (warp & 1) * 64;     // 2 N stripes of 64

    const uint32_t As_base = (uint32_t)__cvta_generic_to_shared(As);
    const uint32_t Bs_base = (uint32_t)__cvta_generic_to_shared(Bs);

    // ---- load A once (cp.async, XOR-swizzled) ----
    {
        const __half* srcA = g_W + (size_t)(mhalf * MTILE) * MEM;
#pragma unroll
        for (int j = 0; j < 32; j++) {
            int i = tid + j * GT;                // 8192 granules of 16B
            int m = i >> 5, gs = i & 31;
            uint32_t sa = As_base + (uint32_t)(m * 512 + ((gs ^ (m & 7)) << 4));
            const __half* gp = srcA + m * MEM + gs * 8;
            asm volatile("cp.async.cg.shared.global [%0], [%1], 16;" :: "r"(sa), "l"(gp) : "memory");
        }
        asm volatile("cp.async.commit_group;" ::: "memory");
    }

    const int nch   = (NCHUNKS - pidx + pairs - 1) / pairs;
    const int total = nch * 4;           // 64-K slabs for this CTA

    // ---- B staging: slab = 64 rows x 128 cols fp32 = 2048 float4 ----
    const float4* membase = reinterpret_cast<const float4*>(memory);
    float4 br[4];

    auto ldg_half = [&](int tt, int h) {
        const int c  = pidx + (tt >> 2) * pairs;
        const int kc = tt & 3;
        const float4* src = membase + (size_t)(kc * 64) * (NCOL / 4) + (size_t)c * 32;
#pragma unroll
        for (int q = 0; q < 4; q++) {
            int i = tid + (q + 4 * h) * GT;
            br[q] = __ldg(&src[(size_t)(i >> 5) * (NCOL / 4) + (i & 31)]);
        }
    };
    auto sts_half = [&](int tt, int h) {
        const int buf = tt & 1;
#pragma unroll
        for (int q = 0; q < 4; q++) {
            int i = tid + (q + 4 * h) * GT;
            int r = i >> 5, c4 = i & 31;
            __half2 h0 = __floats2half2_rn(br[q].x, br[q].y);
            __half2 h1 = __floats2half2_rn(br[q].z, br[q].w);
            uint2* dp = reinterpret_cast<uint2*>(Bs + buf * B_SLAB + r * BPAD + c4 * 4);
            *dp = make_uint2(*reinterpret_cast<uint32_t*>(&h0),
                             *reinterpret_cast<uint32_t*>(&h1));
        }
    };
    // one 128B line per thread = full 32KB slab into L2
    auto prefetch_slab = [&](int tt) {
        const int c  = pidx + (tt >> 2) * pairs;
        const int kc = tt & 3;
        const float* p = memory + (size_t)(kc * 64 + (tid >> 2)) * NCOL
                       + (size_t)c * NCHUNK + (tid & 3) * 32;
        prefetch_l2(p);
    };

    // ---- prologue: stage slab 0 fully, pre-issue ldg(1,h0), wait A ----
    ldg_half(0, 0); sts_half(0, 0);
    ldg_half(0, 1); sts_half(0, 1);
    if (total > 1) ldg_half(1, 0);
    if (total > 2) prefetch_slab(2);
    asm volatile("cp.async.wait_group 0;" ::: "memory");
    __syncthreads();

    // A fragment row bases (swizzle applied per-k at use)
    uint32_t a_row[4], am7[4];
#pragma unroll
    for (int mi = 0; mi < 4; mi++) {
        int m = mw + mi * 16 + (lane & 15);
        a_row[mi] = As_base + (uint32_t)(m * 512);
        am7[mi]   = (uint32_t)(m & 7);
    }
    // B ldmatrix lane offset (bytes within a slab)
    const int bgrp = lane >> 3;
    const uint32_t b_lane_off =
        (uint32_t)(((bgrp & 1) * 8 + (lane & 7)) * (BPAD * 2) + (nw + (bgrp >> 1) * 8) * 2);

    float d[4][8][4];
#pragma unroll
    for (int mi = 0; mi < 4; mi++)
#pragma unroll
        for (int ni = 0; ni < 8; ni++)
#pragma unroll
            for (int r = 0; r < 4; r++) d[mi][ni][r] = 0.f;

    int c = pidx;
    for (int t = 0; t < total; t++) {
        const int  kc   = t & 3;
        const bool more = (t + 1 < total);
        const uint32_t bbase = Bs_base + (uint32_t)((t & 1) * B_SLAB * 2) + b_lane_off;

#pragma unroll
        for (int ks = 0; ks < 4; ks++) {
            // staging schedule: every LDG gets a 2-ks (~900cyc) window, and
            // slabs are L2-prefetched 3 ahead so LDG hits L2.
            if (ks == 0 && more) { sts_half(t + 1, 0); ldg_half(t + 1, 1); }
            if (ks == 1 && t + 3 < total) prefetch_slab(t + 3);
            if (ks == 2 && more) { sts_half(t + 1, 1); if (t + 2 < total) ldg_half(t + 2, 0); }

            uint32_t bf[16];
#pragma unroll
            for (int j = 0; j < 4; j++)
                ldsm_x4_t(bf + 4 * j, bbase + ks * (16 * BPAD * 2) + j * 32);
            const uint32_t gk = (uint32_t)(kc * 8 + ks * 2 + gl);
#pragma unroll
            for (int mi = 0; mi < 4; mi++) {
                uint32_t a[4];
                ldsm_x4(a, a_row[mi] + ((gk ^ am7[mi]) << 4));
#pragma unroll
                for (int j = 0; j < 4; j++) {
                    mma16816(d[mi][2 * j],     a[0], a[1], a[2], a[3], bf[4 * j],     bf[4 * j + 1]);
                    mma16816(d[mi][2 * j + 1], a[0], a[1], a[2], a[3], bf[4 * j + 2], bf[4 * j + 3]);
                }
            }
        }

        if (kc == 3) {
            // epilogue for chunk c: streaming stores, reset accumulators
            const size_t cbase = (size_t)c * NCHUNK;
            const int mbase = mhalf * MTILE;
#pragma unroll
            for (int mi = 0; mi < 4; mi++) {
                const int r0 = mbase + mw + mi * 16 + g;
#pragma unroll
                for (int ni = 0; ni < 8; ni++) {
                    const size_t col = cbase + nw + ni * 8 + tg * 2;
                    stg_cs_v2(out + (size_t)r0 * NCOL + col,
                              make_float2(d[mi][ni][0], d[mi][ni][1]));
                    stg_cs_v2(out + (size_t)(r0 + 8) * NCOL + col,
                              make_float2(d[mi][ni][2], d[mi][ni][3]));
#pragma unroll
                    for (int r = 0; r < 4; r++) d[mi][ni][r] = 0.f;
                }
            }
            c += pairs;
        }

        __syncthreads();   // next slab's fp16 buffer fully written
    }
}

// ---------------------------------------------------------------------------
extern "C" void kernel_launch(void* const* d_in, const int* in_sizes, int n_in,
                              void* d_out, int out_size) {
    const float* features = (const float*)d_in[0];
    const float* keys     = (const float*)d_in[1];
    const float* memory   = (const float*)d_in[2];
    float*       out      = (float*)d_out;

    int sms = 148;
    cudaDeviceGetAttribute(&sms, cudaDevAttrMultiProcessorCount, 0);

    cudaFuncSetAttribute(gemm_kernel,
                         cudaFuncAttributeMaxDynamicSharedMemorySize, DYN_SMEM);

    topk_kernel<<<BATCH / 4, 256>>>(features, keys);
    gemm_kernel<<<2 * sms, GT, DYN_SMEM>>>(memory, out, sms);
}

// round 13
// speedup vs baseline: 1.3190x; 1.0490x over previous
#include <cuda_runtime.h>
#include <cuda_fp16.h>
#include <cstdint>

#define BATCH   512
#define MEM     256            // K dimension
#define FEAT    512
#define NCOL    131072         // 64*2048
#define TOPK    16

#define NCHUNK  128            // N columns per gemm work item
#define NCHUNKS (NCOL / NCHUNK)     // 1024
#define MTILE   256            // M rows per gemm CTA (one half)
#define GT      512            // gemm threads (16 warps)

#define BPAD    136            // halfs per B k-row in smem (128 + 8)
#define B_SLAB  (64 * BPAD)    // halfs per 64-K fp16 B slab (8704)
#define A_HALFS (MTILE * MEM)  // 65536 halfs = 131072 B, swizzled, no pad
#define DYN_SMEM ((A_HALFS + 2 * B_SLAB) * 2)   // 165888 bytes

// Dense fp16 weight matrix W[512][256] (built by topk kernel)
__device__ __align__(16) __half g_W[BATCH * MEM];

// ---------------------------------------------------------------------------
// Kernel 1: cosine sim + top-16 + clamp + renormalize -> dense fp16 W.
// (proven since R4)
// ---------------------------------------------------------------------------
__global__ void __launch_bounds__(256)
topk_kernel(const float* __restrict__ features, const float* __restrict__ keys) {
    __shared__ float f_s[4 * FEAT];
    __shared__ float fn_s[4];
    __shared__ float sim_s[4 * 264];
    __shared__ float topv_s[4][TOPK];
    __shared__ int   topi_s[4][TOPK];
    __shared__ float w_dense[4][MEM];

    const int t    = threadIdx.x;
    const int warp = t >> 5;
    const int lane = t & 31;
    const int base = blockIdx.x * 4;

    float4* f4s = reinterpret_cast<float4*>(f_s);
    const float4* fg = reinterpret_cast<const float4*>(features) + (size_t)base * (FEAT / 4);
    for (int i = t; i < 4 * FEAT / 4; i += 256) f4s[i] = fg[i];
    __syncthreads();

    if (warp < 4) {
        float s = 0.f;
#pragma unroll
        for (int m = 0; m < FEAT / 32; m++) {
            float v = f_s[warp * FEAT + lane + m * 32];
            s += v * v;
        }
#pragma unroll
        for (int off = 16; off; off >>= 1) s += __shfl_down_sync(0xffffffffu, s, off);
        if (lane == 0) fn_s[warp] = fmaxf(sqrtf(s), 1e-8f);
    }
    __syncthreads();

    const float4* krow = reinterpret_cast<const float4*>(keys) + (size_t)t * (FEAT / 4);
    float acc[4] = {0.f, 0.f, 0.f, 0.f};
    float kn = 0.f;
#pragma unroll 4
    for (int dd = 0; dd < FEAT / 4; dd++) {
        float4 kv = krow[dd];
        kn += kv.x * kv.x + kv.y * kv.y + kv.z * kv.z + kv.w * kv.w;
#pragma unroll
        for (int b = 0; b < 4; b++) {
            float4 fv = f4s[b * (FEAT / 4) + dd];
            acc[b] += kv.x * fv.x + kv.y * fv.y + kv.z * fv.z + kv.w * fv.w;
        }
    }
    const float rkn = fmaxf(sqrtf(kn), 1e-8f);
#pragma unroll
    for (int b = 0; b < 4; b++)
        sim_s[b * 264 + t] = acc[b] / (fn_s[b] * rkn);

#pragma unroll
    for (int r = 0; r < 4; r++) w_dense[r][t] = 0.f;
    __syncthreads();

    if (warp < 4) {
        float v[8];
#pragma unroll
        for (int m = 0; m < 8; m++) v[m] = sim_s[warp * 264 + lane * 8 + m];

        for (int k = 0; k < TOPK; k++) {
            float best = v[0];
            int bm = 0;
#pragma unroll
            for (int m = 1; m < 8; m++)
                if (v[m] > best) { best = v[m]; bm = m; }
            int gi = lane * 8 + bm;
#pragma unroll
            for (int off = 16; off; off >>= 1) {
                float ov = __shfl_down_sync(0xffffffffu, best, off);
                int   oi = __shfl_down_sync(0xffffffffu, gi,   off);
                if (ov > best || (ov == best && oi < gi)) { best = ov; gi = oi; }
            }
            best = __shfl_sync(0xffffffffu, best, 0);
            gi   = __shfl_sync(0xffffffffu, gi,   0);
            if (lane == (gi >> 3)) {
                int li = gi & 7;
#pragma unroll
                for (int m = 0; m < 8; m++)
                    if (m == li) v[m] = -3.0e38f;
            }
            if (lane == 0) { topv_s[warp][k] = best; topi_s[warp][k] = gi; }
        }
        __syncwarp();

        float tv = (lane < TOPK) ? fmaxf(topv_s[warp][lane], 0.f) : 0.f;
        float s = tv;
#pragma unroll
        for (int off = 16; off; off >>= 1) s += __shfl_down_sync(0xffffffffu, s, off);
        s = __shfl_sync(0xffffffffu, s, 0);
        const float inv = 1.0f / s;
        if (lane < TOPK)
            w_dense[warp][topi_s[warp][lane]] = tv * inv;
    }
    __syncthreads();

#pragma unroll
    for (int r = 0; r < 4; r++)
        g_W[(base + r) * MEM + t] = __float2half_rn(w_dense[r][t]);
}

// ---------------------------------------------------------------------------
// Kernel 2: persistent HMMA GEMM, 16 warps, warp tile 64M x 32N.
// Same CTA tile (256M x 128N) / SMEM / slab pipeline as R11, but twice the
// warps per SMSP for latency hiding. A loaded once (XOR-swizzled, cp.async);
// B slabs staged fp32->fp16 in-loop with 2-ks LDG windows + L2 prefetch;
// CTA pairs (2p,2p+1) walk identical chunk lists => B's 2nd read hits L2.
// ---------------------------------------------------------------------------
__device__ __forceinline__ void mma16816(float d[4],
                                         uint32_t a0, uint32_t a1, uint32_t a2, uint32_t a3,
                                         uint32_t b0, uint32_t b1) {
    asm volatile(
        "mma.sync.aligned.m16n8k16.row.col.f32.f16.f16.f32 "
        "{%0,%1,%2,%3}, {%4,%5,%6,%7}, {%8,%9}, {%0,%1,%2,%3};"
        : "+f"(d[0]), "+f"(d[1]), "+f"(d[2]), "+f"(d[3])
        : "r"(a0), "r"(a1), "r"(a2), "r"(a3), "r"(b0), "r"(b1));
}
__device__ __forceinline__ void ldsm_x4(uint32_t r[4], uint32_t sa) {
    asm volatile("ldmatrix.sync.aligned.m8n8.x4.shared.b16 {%0,%1,%2,%3}, [%4];"
        : "=r"(r[0]), "=r"(r[1]), "=r"(r[2]), "=r"(r[3]) : "r"(sa));
}
__device__ __forceinline__ void ldsm_x4_t(uint32_t r[4], uint32_t sa) {
    asm volatile("ldmatrix.sync.aligned.m8n8.x4.trans.shared.b16 {%0,%1,%2,%3}, [%4];"
        : "=r"(r[0]), "=r"(r[1]), "=r"(r[2]), "=r"(r[3]) : "r"(sa));
}
__device__ __forceinline__ void stg_cs_v2(float* p, float2 v) {
    asm volatile("st.global.cs.v2.f32 [%0], {%1, %2};" :: "l"(p), "f"(v.x), "f"(v.y) : "memory");
}
__device__ __forceinline__ void prefetch_l2(const void* p) {
    asm volatile("prefetch.global.L2 [%0];" :: "l"(p));
}

__global__ void __launch_bounds__(GT, 1)
gemm_kernel(const float* __restrict__ memory, float* __restrict__ out, int pairs) {
    extern __shared__ __half sm[];
    __half* As = sm;                    // [256][256] swizzled (no pad)
    __half* Bs = sm + A_HALFS;          // [2][64][BPAD]

    const int tid   = threadIdx.x;
    const int warp  = tid >> 5;
    const int lane  = tid & 31;
    const int g     = lane >> 2;
    const int tg    = lane & 3;
    const int gl    = lane >> 4;
    const int mhalf = blockIdx.x & 1;
    const int pidx  = blockIdx.x >> 1;

    const int mw = (warp >> 2) * 64;    // 4 M stripes of 64
    const int nw = (warp & 3) * 32;     // 4 N stripes of 32

    const uint32_t As_base = (uint32_t)__cvta_generic_to_shared(As);
    const uint32_t Bs_base = (uint32_t)__cvta_generic_to_shared(Bs);

    // ---- load A once (cp.async, XOR-swizzled) ----
    {
        const __half* srcA = g_W + (size_t)(mhalf * MTILE) * MEM;
#pragma unroll
        for (int j = 0; j < 16; j++) {
            int i = tid + j * GT;                // 8192 granules of 16B
            int m = i >> 5, gs = i & 31;
            uint32_t sa = As_base + (uint32_t)(m * 512 + ((gs ^ (m & 7)) << 4));
            const __half* gp = srcA + m * MEM + gs * 8;
            asm volatile("cp.async.cg.shared.global [%0], [%1], 16;" :: "r"(sa), "l"(gp) : "memory");
        }
        asm volatile("cp.async.commit_group;" ::: "memory");
    }

    const int nch   = (NCHUNKS - pidx + pairs - 1) / pairs;
    const int total = nch * 4;           // 64-K slabs for this CTA

    // ---- B staging: slab = 64 rows x 128 cols fp32 = 2048 float4 ----
    // 512 threads x 4 granules; half h covers q = 2h .. 2h+1 (rows split).
    const float4* membase = reinterpret_cast<const float4*>(memory);
    float4 br[2];

    auto ldg_half = [&](int tt, int h) {
        const int c  = pidx + (tt >> 2) * pairs;
        const int kc = tt & 3;
        const float4* src = membase + (size_t)(kc * 64) * (NCOL / 4) + (size_t)c * 32;
#pragma unroll
        for (int q = 0; q < 2; q++) {
            int i = tid + (q + 2 * h) * GT;
            br[q] = __ldg(&src[(size_t)(i >> 5) * (NCOL / 4) + (i & 31)]);
        }
    };
    auto sts_half = [&](int tt, int h) {
        const int buf = tt & 1;
#pragma unroll
        for (int q = 0; q < 2; q++) {
            int i = tid + (q + 2 * h) * GT;
            int r = i >> 5, c4 = i & 31;
            __half2 h0 = __floats2half2_rn(br[q].x, br[q].y);
            __half2 h1 = __floats2half2_rn(br[q].z, br[q].w);
            uint2* dp = reinterpret_cast<uint2*>(Bs + buf * B_SLAB + r * BPAD + c4 * 4);
            *dp = make_uint2(*reinterpret_cast<uint32_t*>(&h0),
                             *reinterpret_cast<uint32_t*>(&h1));
        }
    };
    // 512 threads x one 64B prefetch = full 32KB slab into L2
    auto prefetch_slab = [&](int tt) {
        const int c  = pidx + (tt >> 2) * pairs;
        const int kc = tt & 3;
        const float* p = memory + (size_t)(kc * 64 + (tid >> 3)) * NCOL
                       + (size_t)c * NCHUNK + (tid & 7) * 16;
        prefetch_l2(p);
    };

    // ---- prologue: stage slab 0 fully, pre-issue ldg(1,h0), wait A ----
    ldg_half(0, 0); sts_half(0, 0);
    ldg_half(0, 1); sts_half(0, 1);
    if (total > 1) ldg_half(1, 0);
    if (total > 2) prefetch_slab(2);
    asm volatile("cp.async.wait_group 0;" ::: "memory");
    __syncthreads();

    // A fragment row bases (swizzle applied per-k at use)
    uint32_t a_row[4], am7[4];
#pragma unroll
    for (int mi = 0; mi < 4; mi++) {
        int m = mw + mi * 16 + (lane & 15);
        a_row[mi] = As_base + (uint32_t)(m * 512);
        am7[mi]   = (uint32_t)(m & 7);
    }
    // B ldmatrix lane offset (bytes within a slab)
    const int bgrp = lane >> 3;
    const uint32_t b_lane_off =
        (uint32_t)(((bgrp & 1) * 8 + (lane & 7)) * (BPAD * 2) + (nw + (bgrp >> 1) * 8) * 2);

    float d[4][4][4];
#pragma unroll
    for (int mi = 0; mi < 4; mi++)
#pragma unroll
        for (int ni = 0; ni < 4; ni++)
#pragma unroll
            for (int r = 0; r < 4; r++) d[mi][ni][r] = 0.f;

    int c = pidx;
    for (int t = 0; t < total; t++) {
        const int  kc   = t & 3;
        const bool more = (t + 1 < total);
        const uint32_t bbase = Bs_base + (uint32_t)((t & 1) * B_SLAB * 2) + b_lane_off;

#pragma unroll
        for (int ks = 0; ks < 4; ks++) {
            // staging schedule: every LDG gets a 2-ks window; slabs are
            // L2-prefetched 3 ahead so LDG hits L2 (~250cyc << window).
            if (ks == 0 && more) { sts_half(t + 1, 0); ldg_half(t + 1, 1); }
            if (ks == 1 && t + 3 < total) prefetch_slab(t + 3);
            if (ks == 2 && more) { sts_half(t + 1, 1); if (t + 2 < total) ldg_half(t + 2, 0); }

            uint32_t bf[8];
            ldsm_x4_t(bf,     bbase + ks * (16 * BPAD * 2));
            ldsm_x4_t(bf + 4, bbase + ks * (16 * BPAD * 2) + 32);
            const uint32_t gk = (uint32_t)(kc * 8 + ks * 2 + gl);
#pragma unroll
            for (int mi = 0; mi < 4; mi++) {
                uint32_t a[4];
                ldsm_x4(a, a_row[mi] + ((gk ^ am7[mi]) << 4));
                mma16816(d[mi][0], a[0], a[1], a[2], a[3], bf[0], bf[1]);
                mma16816(d[mi][1], a[0], a[1], a[2], a[3], bf[2], bf[3]);
                mma16816(d[mi][2], a[0], a[1], a[2], a[3], bf[4], bf[5]);
                mma16816(d[mi][3], a[0], a[1], a[2], a[3], bf[6], bf[7]);
            }
        }

        if (kc == 3) {
            // epilogue for chunk c: streaming stores, reset accumulators
            const size_t cbase = (size_t)c * NCHUNK;
            const int mbase = mhalf * MTILE;
#pragma unroll
            for (int mi = 0; mi < 4; mi++) {
                const int r0 = mbase + mw + mi * 16 + g;
#pragma unroll
                for (int ni = 0; ni < 4; ni++) {
                    const size_t col = cbase + nw + ni * 8 + tg * 2;
                    stg_cs_v2(out + (size_t)r0 * NCOL + col,
                              make_float2(d[mi][ni][0], d[mi][ni][1]));
                    stg_cs_v2(out + (size_t)(r0 + 8) * NCOL + col,
                              make_float2(d[mi][ni][2], d[mi][ni][3]));
#pragma unroll
                    for (int r = 0; r < 4; r++) d[mi][ni][r] = 0.f;
                }
            }
            c += pairs;
        }

        __syncthreads();   // next slab's fp16 buffer fully written
    }
}

// ---------------------------------------------------------------------------
extern "C" void kernel_launch(void* const* d_in, const int* in_sizes, int n_in,
                              void* d_out, int out_size) {
    const float* features = (const float*)d_in[0];
    const float* keys     = (const float*)d_in[1];
    const float* memory   = (const float*)d_in[2];
    float*       out      = (float*)d_out;

    int sms = 148;
    cudaDeviceGetAttribute(&sms, cudaDevAttrMultiProcessorCount, 0);

    cudaFuncSetAttribute(gemm_kernel,
                         cudaFuncAttributeMaxDynamicSharedMemorySize, DYN_SMEM);

    topk_kernel<<<BATCH / 4, 256>>>(features, keys);
    gemm_kernel<<<2 * sms, GT, DYN_SMEM>>>(memory, out, sms);
}